// round 4
// baseline (speedup 1.0000x reference)
#include <cuda_runtime.h>

#define NN   50000
#define EE   800000
#define EPE  850000          // edges + self loops
#define FIN  256
#define HIDN 64
#define NH   4
#define C1   256             // NH*HIDN
#define NEGS 0.2f
#define LNEPS 1e-5f

// ---------------- scratch (device globals: allocation-free) ----------------
__device__ __align__(16) float    g_h1[NN * C1];      // gat1 features (pre-agg)
__device__ __align__(16) float    g_out1[NN * C1];    // gat1 accum -> hA
__device__ __align__(16) float    g_asrc1[NN * NH];
__device__ __align__(16) float    g_adst1[NN * NH];
__device__ __align__(16) unsigned g_max1[NN * NH];
__device__ __align__(16) float    g_sum1[NN * NH];
__device__ __align__(16) float    g_h2[NN * HIDN];    // gat2 features
__device__ __align__(16) float    g_out2[NN * HIDN];  // gat2 accum
__device__ __align__(16) float    g_asrc2[NN];
__device__ __align__(16) float    g_adst2[NN];
__device__ __align__(16) unsigned g_max2[NN];
__device__ __align__(16) float    g_sum2[NN];
__device__ __align__(16) float    g_res[NN * HIDN];   // x @ lin_w^T

__device__ __forceinline__ float lrelu(float x) { return x > 0.f ? x : NEGS * x; }

// monotone float <-> uint encoding so atomicMax(uint) == float max; 0 == -inf identity
__device__ __forceinline__ unsigned fenc(float f) {
    unsigned u = __float_as_uint(f);
    return (u & 0x80000000u) ? ~u : (u | 0x80000000u);
}
__device__ __forceinline__ float fdec(unsigned u) {
    return (u & 0x80000000u) ? __uint_as_float(u & 0x7fffffffu) : __uint_as_float(~u);
}

// ---------------- C[n,m] = sum_k A[n,k] * W[m,k]  (A:[nrows,K], W:[M,K]) ----
__global__ __launch_bounds__(256) void sgemm_nt(
    const float* __restrict__ A, const float* __restrict__ W,
    float* __restrict__ C, int nrows, int M, int K)
{
    __shared__ __align__(16) float As[16][64];
    __shared__ __align__(16) float Ws[16][64];
    int tid = threadIdx.x;
    int tx = tid & 15, ty = tid >> 4;
    int rowBase = blockIdx.x * 64, colBase = blockIdx.y * 64;
    int lr = tid >> 2, lc = (tid & 3) << 2;
    float acc[4][4] = {};
    for (int k0 = 0; k0 < K; k0 += 16) {
        int ar = rowBase + lr;
        float4 av = make_float4(0.f, 0.f, 0.f, 0.f);
        if (ar < nrows) av = *(const float4*)(A + (size_t)ar * K + k0 + lc);
        As[lc][lr] = av.x; As[lc + 1][lr] = av.y; As[lc + 2][lr] = av.z; As[lc + 3][lr] = av.w;
        float4 wv = *(const float4*)(W + (size_t)(colBase + lr) * K + k0 + lc);
        Ws[lc][lr] = wv.x; Ws[lc + 1][lr] = wv.y; Ws[lc + 2][lr] = wv.z; Ws[lc + 3][lr] = wv.w;
        __syncthreads();
#pragma unroll
        for (int kk = 0; kk < 16; kk++) {
            float4 a4 = *(const float4*)&As[kk][ty * 4];
            float4 b4 = *(const float4*)&Ws[kk][tx * 4];
            float a[4] = {a4.x, a4.y, a4.z, a4.w};
            float b[4] = {b4.x, b4.y, b4.z, b4.w};
#pragma unroll
            for (int i = 0; i < 4; i++)
#pragma unroll
                for (int j = 0; j < 4; j++)
                    acc[i][j] = fmaf(a[i], b[j], acc[i][j]);
        }
        __syncthreads();
    }
#pragma unroll
    for (int i = 0; i < 4; i++) {
        int r = rowBase + ty * 4 + i;
        if (r < nrows) {
#pragma unroll
            for (int j = 0; j < 4; j++)
                C[(size_t)r * M + colBase + tx * 4 + j] = acc[i][j];
        }
    }
}

// --------------- per-(node,head) attention dots: warp per (n,h) ------------
template <int H>
__global__ __launch_bounds__(256) void attn_dots(
    const float* __restrict__ h, const float* __restrict__ att_src,
    const float* __restrict__ att_dst, float* __restrict__ asrc, float* __restrict__ adst)
{
    int wid = (blockIdx.x * blockDim.x + threadIdx.x) >> 5;
    int lane = threadIdx.x & 31;
    if (wid >= NN * H) return;
    int n = wid / H, hd = wid % H;
    const float* hp = h + (size_t)n * (H * HIDN) + hd * HIDN;
    float h0 = hp[lane], h1 = hp[lane + 32];
    float s = h0 * att_src[hd * HIDN + lane] + h1 * att_src[hd * HIDN + lane + 32];
    float d = h0 * att_dst[hd * HIDN + lane] + h1 * att_dst[hd * HIDN + lane + 32];
#pragma unroll
    for (int o = 16; o; o >>= 1) {
        s += __shfl_xor_sync(0xffffffffu, s, o);
        d += __shfl_xor_sync(0xffffffffu, d, o);
    }
    if (lane == 0) { asrc[wid] = s; adst[wid] = d; }
}

// --------------- edge pass 1: segment max of leaky(asrc+adst) --------------
template <int H>
__global__ __launch_bounds__(256) void edge_max_k(
    const int* __restrict__ ei, const float* __restrict__ asrc,
    const float* __restrict__ adst, unsigned* __restrict__ mx)
{
    int e = blockIdx.x * blockDim.x + threadIdx.x;
    if (e >= EPE) return;
    int s, d;
    if (e < EE) { s = ei[e]; d = ei[EE + e]; } else { s = d = e - EE; }
#pragma unroll
    for (int hh = 0; hh < H; hh++) {
        float v = lrelu(asrc[s * H + hh] + adst[d * H + hh]);
        atomicMax(&mx[d * H + hh], fenc(v));
    }
}

// --------------- edge pass 2 (GAT1): w = exp(e-m); sum += w; out += w*h[src]
__global__ __launch_bounds__(256) void edge_accum1(const int* __restrict__ ei)
{
    int t = blockIdx.x * blockDim.x + threadIdx.x;
    int wid = t >> 5, lane = t & 31;
    if (wid >= EPE) return;
    int s, d;
    if (wid < EE) { s = ei[wid]; d = ei[EE + wid]; } else { s = d = wid - EE; }
    float w = 0.f;
    if (lane < NH) {
        float v = lrelu(g_asrc1[s * NH + lane] + g_adst1[d * NH + lane]);
        float m = fdec(g_max1[d * NH + lane]);
        w = __expf(v - m);
        atomicAdd(&g_sum1[d * NH + lane], w);
    }
    // channels lane*4..+3 belong to head lane>>4; channels 128+lane*4 to head 2+(lane>>4)
    float wa = __shfl_sync(0xffffffffu, w, lane >> 4);
    float wb = __shfl_sync(0xffffffffu, w, 2 + (lane >> 4));
    const float4* hs = (const float4*)(g_h1 + (size_t)s * C1);
    float4 va = hs[lane];
    float4 vb = hs[32 + lane];
    float* oa = g_out1 + (size_t)d * C1 + lane * 4;
    float* ob = oa + 128;
    asm volatile("red.global.add.v4.f32 [%0], {%1,%2,%3,%4};" ::
                 "l"(oa), "f"(va.x * wa), "f"(va.y * wa), "f"(va.z * wa), "f"(va.w * wa) : "memory");
    asm volatile("red.global.add.v4.f32 [%0], {%1,%2,%3,%4};" ::
                 "l"(ob), "f"(vb.x * wb), "f"(vb.y * wb), "f"(vb.z * wb), "f"(vb.w * wb) : "memory");
}

// --------------- hA = leaky(out1/sum + b1), in place -----------------------
__global__ __launch_bounds__(256) void finalize1(const float* __restrict__ b1)
{
    int idx = blockIdx.x * blockDim.x + threadIdx.x;
    if (idx >= NN * C1) return;
    int c = idx & 255, n = idx >> 8, hd = c >> 6;
    float v = g_out1[idx] / g_sum1[n * NH + hd] + b1[c];
    g_out1[idx] = lrelu(v);
}

// --------------- edge pass 2 (GAT2), 1 head, 64 channels -------------------
__global__ __launch_bounds__(256) void edge_accum2(const int* __restrict__ ei)
{
    int t = blockIdx.x * blockDim.x + threadIdx.x;
    int wid = t >> 5, lane = t & 31;
    if (wid >= EPE) return;
    int s, d;
    if (wid < EE) { s = ei[wid]; d = ei[EE + wid]; } else { s = d = wid - EE; }
    float w = 0.f;
    if (lane == 0) {
        float v = lrelu(g_asrc2[s] + g_adst2[d]);
        float m = fdec(g_max2[d]);
        w = __expf(v - m);
        atomicAdd(&g_sum2[d], w);
    }
    w = __shfl_sync(0xffffffffu, w, 0);
    float2 hv = ((const float2*)(g_h2 + (size_t)s * HIDN))[lane];
    float* o = g_out2 + (size_t)d * HIDN + lane * 2;
    asm volatile("red.global.add.v2.f32 [%0], {%1,%2};" ::
                 "l"(o), "f"(hv.x * w), "f"(hv.y * w) : "memory");
}

// --------------- fused: leaky+LN+residual+GRU+fc; warp per node ------------
__global__ __launch_bounds__(256) void final_kernel(
    const float* __restrict__ b2, const float* __restrict__ gamma, const float* __restrict__ beta,
    const float* __restrict__ lin_b, const float* __restrict__ w_ih, const float* __restrict__ b_ih,
    const float* __restrict__ b_hh, const float* __restrict__ fc_w, const float* __restrict__ fc_b,
    float* __restrict__ out)
{
    __shared__ float w_ihs[64 * 192];   // transposed: [j][g], 48KB
    int tid = threadIdx.x;
    for (int i = tid; i < 64 * 192; i += 256) {
        int g = i / 64, j = i % 64;
        w_ihs[j * 192 + g] = w_ih[i];
    }
    __syncthreads();
    int lane = tid & 31;
    int node = blockIdx.x * 8 + (tid >> 5);
    if (node >= NN) return;
    int j0 = lane, j1 = lane + 32;
    float inv = 1.f / g_sum2[node];
    float h0 = lrelu(g_out2[node * HIDN + j0] * inv + b2[j0]);
    float h1 = lrelu(g_out2[node * HIDN + j1] * inv + b2[j1]);
    // LayerNorm over 64 (biased var)
    float s = h0 + h1;
#pragma unroll
    for (int o = 16; o; o >>= 1) s += __shfl_xor_sync(0xffffffffu, s, o);
    float mu = s * (1.f / 64.f);
    float d0 = h0 - mu, d1 = h1 - mu;
    float v = d0 * d0 + d1 * d1;
#pragma unroll
    for (int o = 16; o; o >>= 1) v += __shfl_xor_sync(0xffffffffu, v, o);
    float rstd = rsqrtf(v * (1.f / 64.f) + LNEPS);
    // + residual + lin_b
    h0 = d0 * rstd * gamma[j0] + beta[j0] + g_res[node * HIDN + j0] + lin_b[j0];
    h1 = d1 * rstd * gamma[j1] + beta[j1] + g_res[node * HIDN + j1] + lin_b[j1];
    // GRU (h_prev = 0): gi = h @ w_ih^T + b_ih;  gates r,z,n
    float gi0 = b_ih[j0],        gi1 = b_ih[j1];
    float gi2 = b_ih[64 + j0],   gi3 = b_ih[64 + j1];
    float gi4 = b_ih[128 + j0],  gi5 = b_ih[128 + j1];
    for (int j = 0; j < 64; j++) {
        float hv = __shfl_sync(0xffffffffu, (j < 32) ? h0 : h1, j & 31);
        const float* wr = &w_ihs[j * 192];
        gi0 = fmaf(hv, wr[j0], gi0);
        gi1 = fmaf(hv, wr[j1], gi1);
        gi2 = fmaf(hv, wr[64 + j0], gi2);
        gi3 = fmaf(hv, wr[64 + j1], gi3);
        gi4 = fmaf(hv, wr[128 + j0], gi4);
        gi5 = fmaf(hv, wr[128 + j1], gi5);
    }
    float r0 = 1.f / (1.f + __expf(-(gi0 + b_hh[j0])));
    float r1 = 1.f / (1.f + __expf(-(gi1 + b_hh[j1])));
    float z0 = 1.f / (1.f + __expf(-(gi2 + b_hh[64 + j0])));
    float z1 = 1.f / (1.f + __expf(-(gi3 + b_hh[64 + j1])));
    float n0 = tanhf(gi4 + r0 * b_hh[128 + j0]);
    float n1 = tanhf(gi5 + r1 * b_hh[128 + j1]);
    float hy0 = (1.f - z0) * n0;
    float hy1 = (1.f - z1) * n1;
    // fc head -> 3 classes
    float p0 = hy0 * fc_w[j0]        + hy1 * fc_w[j1];
    float p1 = hy0 * fc_w[64 + j0]   + hy1 * fc_w[64 + j1];
    float p2 = hy0 * fc_w[128 + j0]  + hy1 * fc_w[128 + j1];
#pragma unroll
    for (int o = 16; o; o >>= 1) {
        p0 += __shfl_xor_sync(0xffffffffu, p0, o);
        p1 += __shfl_xor_sync(0xffffffffu, p1, o);
        p2 += __shfl_xor_sync(0xffffffffu, p2, o);
    }
    if (lane == 0) {
        out[node * 3 + 0] = p0 + fc_b[0];
        out[node * 3 + 1] = p1 + fc_b[1];
        out[node * 3 + 2] = p2 + fc_b[2];
    }
}

// ---------------------------------------------------------------------------
extern "C" void kernel_launch(void* const* d_in, const int* in_sizes, int n_in,
                              void* d_out, int out_size)
{
    const float* x        = (const float*)d_in[0];
    const int*   ei       = (const int*)d_in[1];
    const float* W1       = (const float*)d_in[2];
    const float* att_src1 = (const float*)d_in[3];
    const float* att_dst1 = (const float*)d_in[4];
    const float* b1       = (const float*)d_in[5];
    const float* W2       = (const float*)d_in[6];
    const float* att_src2 = (const float*)d_in[7];
    const float* att_dst2 = (const float*)d_in[8];
    const float* b2       = (const float*)d_in[9];
    const float* lin_w    = (const float*)d_in[10];
    const float* lin_b    = (const float*)d_in[11];
    const float* gamma    = (const float*)d_in[12];
    const float* beta     = (const float*)d_in[13];
    const float* w_ih     = (const float*)d_in[14];
    // d_in[15] = w_hh: unused (h0 == 0 so W_hh @ h0 == 0)
    const float* b_ih     = (const float*)d_in[16];
    const float* b_hh     = (const float*)d_in[17];
    const float* fc_w     = (const float*)d_in[18];
    const float* fc_b     = (const float*)d_in[19];
    float* out = (float*)d_out;

    void* p;
    cudaGetSymbolAddress(&p, g_h1);    float*    ph1   = (float*)p;
    cudaGetSymbolAddress(&p, g_out1);  float*    pout1 = (float*)p;
    cudaGetSymbolAddress(&p, g_sum1);  float*    psum1 = (float*)p;
    cudaGetSymbolAddress(&p, g_max1);  unsigned* pmax1 = (unsigned*)p;
    cudaGetSymbolAddress(&p, g_asrc1); float*    pas1  = (float*)p;
    cudaGetSymbolAddress(&p, g_adst1); float*    pad1  = (float*)p;
    cudaGetSymbolAddress(&p, g_h2);    float*    ph2   = (float*)p;
    cudaGetSymbolAddress(&p, g_out2);  float*    pout2 = (float*)p;
    cudaGetSymbolAddress(&p, g_sum2);  float*    psum2 = (float*)p;
    cudaGetSymbolAddress(&p, g_max2);  unsigned* pmax2 = (unsigned*)p;
    cudaGetSymbolAddress(&p, g_asrc2); float*    pas2  = (float*)p;
    cudaGetSymbolAddress(&p, g_adst2); float*    pad2  = (float*)p;
    cudaGetSymbolAddress(&p, g_res);   float*    pres  = (float*)p;

    cudaMemsetAsync(pout1, 0, sizeof(float) * NN * C1, 0);
    cudaMemsetAsync(psum1, 0, sizeof(float) * NN * NH, 0);
    cudaMemsetAsync(pmax1, 0, sizeof(unsigned) * NN * NH, 0);
    cudaMemsetAsync(pout2, 0, sizeof(float) * NN * HIDN, 0);
    cudaMemsetAsync(psum2, 0, sizeof(float) * NN, 0);
    cudaMemsetAsync(pmax2, 0, sizeof(unsigned) * NN, 0);

    dim3 gg1((NN + 63) / 64, C1 / 64);
    sgemm_nt<<<gg1, 256>>>(x, W1, ph1, NN, C1, FIN);                 // h1 = x@W1^T
    dim3 ggr((NN + 63) / 64, 1);
    sgemm_nt<<<ggr, 256>>>(x, lin_w, pres, NN, HIDN, FIN);           // res = x@lin_w^T

    attn_dots<NH><<<(NN * NH + 7) / 8, 256>>>(ph1, att_src1, att_dst1, pas1, pad1);
    edge_max_k<NH><<<(EPE + 255) / 256, 256>>>(ei, pas1, pad1, pmax1);
    edge_accum1<<<(EPE + 7) / 8, 256>>>(ei);
    finalize1<<<(NN * C1) / 256, 256>>>(b1);                         // hA in g_out1

    sgemm_nt<<<ggr, 256>>>(pout1, W2, ph2, NN, HIDN, C1);            // h2 = hA@W2^T
    attn_dots<1><<<(NN + 7) / 8, 256>>>(ph2, att_src2, att_dst2, pas2, pad2);
    edge_max_k<1><<<(EPE + 255) / 256, 256>>>(ei, pas2, pad2, pmax2);
    edge_accum2<<<(EPE + 7) / 8, 256>>>(ei);

    final_kernel<<<NN / 8, 256>>>(b2, gamma, beta, lin_b, w_ih, b_ih, b_hh, fc_w, fc_b, out);
}

// round 8
// speedup vs baseline: 1.3126x; 1.3126x over previous
#include <cuda_runtime.h>

#define NN   50000
#define EE   800000
#define EPE  850000          // edges + self loops
#define FIN  256
#define HIDN 64
#define NH   4
#define C1   256             // NH*HIDN
#define NEGS 0.2f
#define LNEPS 1e-5f

// ---------------- scratch (device globals: allocation-free) ----------------
__device__ __align__(16) float g_h1[NN * C1];      // gat1 per-node features (pre-agg)
__device__ __align__(16) float g_hA[NN * C1];      // gat1 aggregated+activated
__device__ __align__(16) float g_asrc1[NN * NH];
__device__ __align__(16) float g_adst1[NN * NH];
__device__ __align__(16) float g_h2[NN * HIDN];    // gat2 per-node features
__device__ __align__(16) float g_h2a[NN * HIDN];   // gat2 aggregated+activated
__device__ __align__(16) float g_asrc2[NN];
__device__ __align__(16) float g_adst2[NN];
__device__ __align__(16) float g_res[NN * HIDN];   // x @ lin_w^T
__device__ __align__(16) int   g_deg[NN];
__device__ __align__(16) int   g_off[NN + 1];
__device__ __align__(16) int   g_cur[NN];
__device__ __align__(16) int   g_csr_src[EPE];

__device__ __forceinline__ float lrelu(float x) { return x > 0.f ? x : NEGS * x; }

// ================= CSR build =================
__global__ __launch_bounds__(256) void csr_count(const int* __restrict__ ei)
{
    int e = blockIdx.x * blockDim.x + threadIdx.x;
    if (e >= EPE) return;
    int d = (e < EE) ? ei[EE + e] : (e - EE);
    atomicAdd(&g_deg[d], 1);
}

__global__ __launch_bounds__(1024) void csr_scan()   // single block
{
    __shared__ int warp_sums[32];
    __shared__ int s_carry;
    int tid = threadIdx.x, lane = tid & 31, wid = tid >> 5;
    if (tid == 0) s_carry = 0;
    __syncthreads();
    for (int base = 0; base < NN; base += 1024) {
        int i = base + tid;
        int v = (i < NN) ? g_deg[i] : 0;
        int x = v;
#pragma unroll
        for (int o = 1; o < 32; o <<= 1) {
            int y = __shfl_up_sync(0xffffffffu, x, o);
            if (lane >= o) x += y;
        }
        if (lane == 31) warp_sums[wid] = x;
        __syncthreads();
        if (wid == 0) {
            int ws = warp_sums[lane];
#pragma unroll
            for (int o = 1; o < 32; o <<= 1) {
                int y = __shfl_up_sync(0xffffffffu, ws, o);
                if (lane >= o) ws += y;
            }
            warp_sums[lane] = ws;
        }
        __syncthreads();
        int carry = s_carry;
        int excl = carry + (wid ? warp_sums[wid - 1] : 0) + (x - v);
        if (i < NN) { g_off[i] = excl; g_cur[i] = excl; }
        __syncthreads();
        if (tid == 0) s_carry = carry + warp_sums[31];
        __syncthreads();
    }
    if (tid == 0) g_off[NN] = s_carry;   // == EPE
}

__global__ __launch_bounds__(256) void csr_scatter(const int* __restrict__ ei)
{
    int e = blockIdx.x * blockDim.x + threadIdx.x;
    if (e >= EPE) return;
    int s, d;
    if (e < EE) { s = ei[e]; d = ei[EE + e]; } else { s = d = e - EE; }
    int pos = atomicAdd(&g_cur[d], 1);
    g_csr_src[pos] = s;
}

// ============ SGEMM: C[n,m] = sum_k A[n,k]*W[m,k], K=256 fixed =============
// 128x64 tile, 256 threads, 8x4 microtile, BK=16, double-buffered smem.
__global__ __launch_bounds__(256, 3) void sgemm_opt(
    const float* __restrict__ A, const float* __restrict__ W,
    float* __restrict__ C, int nrows, int M)
{
    const int K = 256;
    __shared__ __align__(16) float As[2][16][128];
    __shared__ __align__(16) float Bs[2][16][64];
    int tid = threadIdx.x;
    int tx = tid & 15, ty = tid >> 4;
    int rowBase = blockIdx.x * 128, colBase = blockIdx.y * 64;

    int arow = tid >> 1, akh = (tid & 1) * 8;       // A loader: 2 float4 per thread
    int bm = tid & 63, bkg = (tid >> 6) * 4;        // B loader: 1 float4 per thread
    bool aOK = (rowBase + arow) < nrows;
    const float* Ap = A + (size_t)(rowBase + arow) * K + akh;
    const float* Bp = W + (size_t)(colBase + bm) * K + bkg;

    float4 a0 = make_float4(0.f, 0.f, 0.f, 0.f), a1 = a0;
    if (aOK) { a0 = *(const float4*)Ap; a1 = *(const float4*)(Ap + 4); }
    float4 b0 = *(const float4*)Bp;

    As[0][akh + 0][arow] = a0.x; As[0][akh + 1][arow] = a0.y;
    As[0][akh + 2][arow] = a0.z; As[0][akh + 3][arow] = a0.w;
    As[0][akh + 4][arow] = a1.x; As[0][akh + 5][arow] = a1.y;
    As[0][akh + 6][arow] = a1.z; As[0][akh + 7][arow] = a1.w;
    Bs[0][bkg + 0][bm] = b0.x; Bs[0][bkg + 1][bm] = b0.y;
    Bs[0][bkg + 2][bm] = b0.z; Bs[0][bkg + 3][bm] = b0.w;
    __syncthreads();

    float acc[8][4] = {};
    int buf = 0;
    for (int kt = 1; kt < K / 16; kt++) {
        float4 na0 = make_float4(0.f, 0.f, 0.f, 0.f), na1 = na0;
        if (aOK) { na0 = *(const float4*)(Ap + kt * 16); na1 = *(const float4*)(Ap + kt * 16 + 4); }
        float4 nb0 = *(const float4*)(Bp + kt * 16);
#pragma unroll
        for (int kk = 0; kk < 16; kk++) {
            float4 af0 = *(const float4*)&As[buf][kk][ty * 8];
            float4 af1 = *(const float4*)&As[buf][kk][ty * 8 + 4];
            float4 bf  = *(const float4*)&Bs[buf][kk][tx * 4];
            float a[8] = {af0.x, af0.y, af0.z, af0.w, af1.x, af1.y, af1.z, af1.w};
            float b[4] = {bf.x, bf.y, bf.z, bf.w};
#pragma unroll
            for (int i = 0; i < 8; i++)
#pragma unroll
                for (int j = 0; j < 4; j++)
                    acc[i][j] = fmaf(a[i], b[j], acc[i][j]);
        }
        int nb = buf ^ 1;
        As[nb][akh + 0][arow] = na0.x; As[nb][akh + 1][arow] = na0.y;
        As[nb][akh + 2][arow] = na0.z; As[nb][akh + 3][arow] = na0.w;
        As[nb][akh + 4][arow] = na1.x; As[nb][akh + 5][arow] = na1.y;
        As[nb][akh + 6][arow] = na1.z; As[nb][akh + 7][arow] = na1.w;
        Bs[nb][bkg + 0][bm] = nb0.x; Bs[nb][bkg + 1][bm] = nb0.y;
        Bs[nb][bkg + 2][bm] = nb0.z; Bs[nb][bkg + 3][bm] = nb0.w;
        __syncthreads();
        buf = nb;
    }
#pragma unroll
    for (int kk = 0; kk < 16; kk++) {
        float4 af0 = *(const float4*)&As[buf][kk][ty * 8];
        float4 af1 = *(const float4*)&As[buf][kk][ty * 8 + 4];
        float4 bf  = *(const float4*)&Bs[buf][kk][tx * 4];
        float a[8] = {af0.x, af0.y, af0.z, af0.w, af1.x, af1.y, af1.z, af1.w};
        float b[4] = {bf.x, bf.y, bf.z, bf.w};
#pragma unroll
        for (int i = 0; i < 8; i++)
#pragma unroll
            for (int j = 0; j < 4; j++)
                acc[i][j] = fmaf(a[i], b[j], acc[i][j]);
    }
#pragma unroll
    for (int i = 0; i < 8; i++) {
        int r = rowBase + ty * 8 + i;
        if (r < nrows)
            *(float4*)(C + (size_t)r * M + colBase + tx * 4) =
                make_float4(acc[i][0], acc[i][1], acc[i][2], acc[i][3]);
    }
}

// --------------- per-(node,head) attention dots: warp per (n,h) ------------
template <int H>
__global__ __launch_bounds__(256) void attn_dots(
    const float* __restrict__ h, const float* __restrict__ att_src,
    const float* __restrict__ att_dst, float* __restrict__ asrc, float* __restrict__ adst)
{
    int wid = (blockIdx.x * blockDim.x + threadIdx.x) >> 5;
    int lane = threadIdx.x & 31;
    if (wid >= NN * H) return;
    int n = wid / H, hd = wid % H;
    const float* hp = h + (size_t)n * (H * HIDN) + hd * HIDN;
    float h0 = hp[lane], h1 = hp[lane + 32];
    float s = h0 * att_src[hd * HIDN + lane] + h1 * att_src[hd * HIDN + lane + 32];
    float d = h0 * att_dst[hd * HIDN + lane] + h1 * att_dst[hd * HIDN + lane + 32];
#pragma unroll
    for (int o = 16; o; o >>= 1) {
        s += __shfl_xor_sync(0xffffffffu, s, o);
        d += __shfl_xor_sync(0xffffffffu, d, o);
    }
    if (lane == 0) { asrc[wid] = s; adst[wid] = d; }
}

// ------ GAT1 aggregation: warp per dst node, register accum, no atomics ----
// softmax without max-shift (logits bounded); fused normalize+bias+leaky.
__global__ __launch_bounds__(256) void gat1_agg(const float* __restrict__ b1)
{
    int t = blockIdx.x * blockDim.x + threadIdx.x;
    int n = t >> 5, lane = t & 31;
    if (n >= NN) return;
    int start = g_off[n], end = g_off[n + 1];
    float adn = (lane < NH) ? g_adst1[n * NH + lane] : 0.f;
    int ha = lane >> 4, hb = 2 + ha;
    float4 acc0 = make_float4(0.f, 0.f, 0.f, 0.f), acc1 = acc0;
    float wsum = 0.f;
    int sNext = g_csr_src[start];           // deg >= 1 (self loop)
    for (int e = start; e < end; e++) {
        int s = sNext;
        if (e + 1 < end) sNext = g_csr_src[e + 1];
        float w = 0.f;
        if (lane < NH) {
            float v = g_asrc1[s * NH + lane] + adn;
            v = v > 0.f ? v : NEGS * v;
            w = __expf(v);
            wsum += w;
        }
        float wa = __shfl_sync(0xffffffffu, w, ha);
        float wb = __shfl_sync(0xffffffffu, w, hb);
        const float4* hp = (const float4*)(g_h1 + (size_t)s * C1);
        float4 va = hp[lane];
        float4 vb = hp[32 + lane];
        acc0.x = fmaf(va.x, wa, acc0.x); acc0.y = fmaf(va.y, wa, acc0.y);
        acc0.z = fmaf(va.z, wa, acc0.z); acc0.w = fmaf(va.w, wa, acc0.w);
        acc1.x = fmaf(vb.x, wb, acc1.x); acc1.y = fmaf(vb.y, wb, acc1.y);
        acc1.z = fmaf(vb.z, wb, acc1.z); acc1.w = fmaf(vb.w, wb, acc1.w);
    }
    float invA = 1.f / __shfl_sync(0xffffffffu, wsum, ha);
    float invB = 1.f / __shfl_sync(0xffffffffu, wsum, hb);
    int ca = lane * 4, cb = 128 + lane * 4;
    float4 o0, o1;
    o0.x = lrelu(acc0.x * invA + b1[ca + 0]); o0.y = lrelu(acc0.y * invA + b1[ca + 1]);
    o0.z = lrelu(acc0.z * invA + b1[ca + 2]); o0.w = lrelu(acc0.w * invA + b1[ca + 3]);
    o1.x = lrelu(acc1.x * invB + b1[cb + 0]); o1.y = lrelu(acc1.y * invB + b1[cb + 1]);
    o1.z = lrelu(acc1.z * invB + b1[cb + 2]); o1.w = lrelu(acc1.w * invB + b1[cb + 3]);
    float4* op = (float4*)(g_hA + (size_t)n * C1);
    op[lane] = o0;
    op[32 + lane] = o1;
}

// ------ GAT2 aggregation: warp per dst node, 1 head, 64 ch -----------------
__global__ __launch_bounds__(256) void gat2_agg(const float* __restrict__ b2)
{
    int t = blockIdx.x * blockDim.x + threadIdx.x;
    int n = t >> 5, lane = t & 31;
    if (n >= NN) return;
    int start = g_off[n], end = g_off[n + 1];
    float adn = g_adst2[n];
    float2 acc = make_float2(0.f, 0.f);
    float wsum = 0.f;
    int sNext = g_csr_src[start];
    for (int e = start; e < end; e++) {
        int s = sNext;
        if (e + 1 < end) sNext = g_csr_src[e + 1];
        float v = g_asrc2[s] + adn;          // broadcast load, all lanes identical
        v = v > 0.f ? v : NEGS * v;
        float w = __expf(v);
        wsum += w;
        float2 hv = ((const float2*)(g_h2 + (size_t)s * HIDN))[lane];
        acc.x = fmaf(hv.x, w, acc.x);
        acc.y = fmaf(hv.y, w, acc.y);
    }
    float inv = 1.f / wsum;
    int c = lane * 2;
    float2 o;
    o.x = lrelu(acc.x * inv + b2[c + 0]);
    o.y = lrelu(acc.y * inv + b2[c + 1]);
    ((float2*)(g_h2a + (size_t)n * HIDN))[lane] = o;
}

// --------------- fused: LN + residual + GRU + fc; warp per node ------------
__global__ __launch_bounds__(256) void final_kernel(
    const float* __restrict__ gamma, const float* __restrict__ beta,
    const float* __restrict__ lin_b, const float* __restrict__ w_ih,
    const float* __restrict__ b_ih, const float* __restrict__ b_hh,
    const float* __restrict__ fc_w, const float* __restrict__ fc_b,
    float* __restrict__ out)
{
    __shared__ float w_ihs[64 * 192];   // transposed: [j][g], 48KB
    int tid = threadIdx.x;
    for (int i = tid; i < 64 * 192; i += 256) {
        int g = i / 64, j = i % 64;
        w_ihs[j * 192 + g] = w_ih[i];
    }
    __syncthreads();
    int lane = tid & 31;
    int node = blockIdx.x * 8 + (tid >> 5);
    int j0 = lane, j1 = lane + 32;
    float h0 = g_h2a[node * HIDN + j0];
    float h1 = g_h2a[node * HIDN + j1];
    // LayerNorm over 64 (biased var)
    float s = h0 + h1;
#pragma unroll
    for (int o = 16; o; o >>= 1) s += __shfl_xor_sync(0xffffffffu, s, o);
    float mu = s * (1.f / 64.f);
    float d0 = h0 - mu, d1 = h1 - mu;
    float v = d0 * d0 + d1 * d1;
#pragma unroll
    for (int o = 16; o; o >>= 1) v += __shfl_xor_sync(0xffffffffu, v, o);
    float rstd = rsqrtf(v * (1.f / 64.f) + LNEPS);
    h0 = d0 * rstd * gamma[j0] + beta[j0] + g_res[node * HIDN + j0] + lin_b[j0];
    h1 = d1 * rstd * gamma[j1] + beta[j1] + g_res[node * HIDN + j1] + lin_b[j1];
    // GRU (h_prev = 0): gi = h @ w_ih^T + b_ih;  gates r,z,n
    float gi0 = b_ih[j0],       gi1 = b_ih[j1];
    float gi2 = b_ih[64 + j0],  gi3 = b_ih[64 + j1];
    float gi4 = b_ih[128 + j0], gi5 = b_ih[128 + j1];
    for (int j = 0; j < 64; j++) {
        float hv = __shfl_sync(0xffffffffu, (j < 32) ? h0 : h1, j & 31);
        const float* wr = &w_ihs[j * 192];
        gi0 = fmaf(hv, wr[j0], gi0);
        gi1 = fmaf(hv, wr[j1], gi1);
        gi2 = fmaf(hv, wr[64 + j0], gi2);
        gi3 = fmaf(hv, wr[64 + j1], gi3);
        gi4 = fmaf(hv, wr[128 + j0], gi4);
        gi5 = fmaf(hv, wr[128 + j1], gi5);
    }
    float r0 = 1.f / (1.f + __expf(-(gi0 + b_hh[j0])));
    float r1 = 1.f / (1.f + __expf(-(gi1 + b_hh[j1])));
    float z0 = 1.f / (1.f + __expf(-(gi2 + b_hh[64 + j0])));
    float z1 = 1.f / (1.f + __expf(-(gi3 + b_hh[64 + j1])));
    float n0 = tanhf(gi4 + r0 * b_hh[128 + j0]);
    float n1 = tanhf(gi5 + r1 * b_hh[128 + j1]);
    float hy0 = (1.f - z0) * n0;
    float hy1 = (1.f - z1) * n1;
    float p0 = hy0 * fc_w[j0]       + hy1 * fc_w[j1];
    float p1 = hy0 * fc_w[64 + j0]  + hy1 * fc_w[64 + j1];
    float p2 = hy0 * fc_w[128 + j0] + hy1 * fc_w[128 + j1];
#pragma unroll
    for (int o = 16; o; o >>= 1) {
        p0 += __shfl_xor_sync(0xffffffffu, p0, o);
        p1 += __shfl_xor_sync(0xffffffffu, p1, o);
        p2 += __shfl_xor_sync(0xffffffffu, p2, o);
    }
    if (lane == 0) {
        out[node * 3 + 0] = p0 + fc_b[0];
        out[node * 3 + 1] = p1 + fc_b[1];
        out[node * 3 + 2] = p2 + fc_b[2];
    }
}

// ---------------------------------------------------------------------------
extern "C" void kernel_launch(void* const* d_in, const int* in_sizes, int n_in,
                              void* d_out, int out_size)
{
    const float* x        = (const float*)d_in[0];
    const int*   ei       = (const int*)d_in[1];
    const float* W1       = (const float*)d_in[2];
    const float* att_src1 = (const float*)d_in[3];
    const float* att_dst1 = (const float*)d_in[4];
    const float* b1       = (const float*)d_in[5];
    const float* W2       = (const float*)d_in[6];
    const float* att_src2 = (const float*)d_in[7];
    const float* att_dst2 = (const float*)d_in[8];
    const float* b2       = (const float*)d_in[9];
    const float* lin_w    = (const float*)d_in[10];
    const float* lin_b    = (const float*)d_in[11];
    const float* gamma    = (const float*)d_in[12];
    const float* beta     = (const float*)d_in[13];
    const float* w_ih     = (const float*)d_in[14];
    // d_in[15] = w_hh: unused (h0 == 0 so W_hh @ h0 == 0)
    const float* b_ih     = (const float*)d_in[16];
    const float* b_hh     = (const float*)d_in[17];
    const float* fc_w     = (const float*)d_in[18];
    const float* fc_b     = (const float*)d_in[19];
    float* out = (float*)d_out;

    void* p;
    cudaGetSymbolAddress(&p, g_h1);    float* ph1  = (float*)p;
    cudaGetSymbolAddress(&p, g_hA);    float* phA  = (float*)p;
    cudaGetSymbolAddress(&p, g_asrc1); float* pas1 = (float*)p;
    cudaGetSymbolAddress(&p, g_adst1); float* pad1 = (float*)p;
    cudaGetSymbolAddress(&p, g_h2);    float* ph2  = (float*)p;
    cudaGetSymbolAddress(&p, g_asrc2); float* pas2 = (float*)p;
    cudaGetSymbolAddress(&p, g_adst2); float* pad2 = (float*)p;
    cudaGetSymbolAddress(&p, g_res);   float* pres = (float*)p;
    cudaGetSymbolAddress(&p, g_deg);   int*   pdeg = (int*)p;

    // ---- CSR build (graph constant per call; shared by both GAT layers) ----
    cudaMemsetAsync(pdeg, 0, sizeof(int) * NN, 0);
    csr_count<<<(EPE + 255) / 256, 256>>>(ei);
    csr_scan<<<1, 1024>>>();
    csr_scatter<<<(EPE + 255) / 256, 256>>>(ei);

    // ---- GEMMs (all K=256) ----
    dim3 gg1((NN + 127) / 128, C1 / 64);
    sgemm_opt<<<gg1, 256>>>(x, W1, ph1, NN, C1);        // h1 = x @ W1^T
    dim3 ggs((NN + 127) / 128, 1);
    sgemm_opt<<<ggs, 256>>>(x, lin_w, pres, NN, HIDN);  // res = x @ lin_w^T

    // ---- GAT1 ----
    attn_dots<NH><<<(NN * NH + 7) / 8, 256>>>(ph1, att_src1, att_dst1, pas1, pad1);
    gat1_agg<<<(NN + 7) / 8, 256>>>(b1);                // -> g_hA (norm+bias+leaky fused)

    // ---- GAT2 ----
    sgemm_opt<<<ggs, 256>>>(phA, W2, ph2, NN, HIDN);    // h2 = hA @ W2^T
    attn_dots<1><<<(NN + 7) / 8, 256>>>(ph2, att_src2, att_dst2, pas2, pad2);
    gat2_agg<<<(NN + 7) / 8, 256>>>(b2);                // -> g_h2a (norm+bias+leaky fused)

    // ---- LN + residual + GRU + fc ----
    final_kernel<<<NN / 8, 256>>>(gamma, beta, lin_b, w_ih, b_ih, b_hh, fc_w, fc_b, out);
}